// round 2
// baseline (speedup 1.0000x reference)
#include <cuda_runtime.h>
#include <cuda_bf16.h>

#define BATCH 4096
#define IN_F 128
#define OUT_F 128
#define NW (IN_F * OUT_F)

// Scratch: 9 repacked generator matrices G_e[o][i] (e=8 holds gen_b weight part),
// plus bias-generator WB[e][o]. Static __device__ arrays (no runtime alloc).
__device__ float d_Gp[9 * 16384];
__device__ float d_WB[9 * 128];

// ---------------------------------------------------------------------------
// Repack: d_Gp[e][o*128+i] = gen_W[(o*128+i)*8 + e]  (e<8),  gen_b[o*128+i] (e=8)
//         d_WB[e][o]       = gen_W[(NW+o)*8 + e]     (e<8),  gen_b[NW+o]    (e=8)
// ---------------------------------------------------------------------------
__global__ void repack_kernel(const float* __restrict__ gen_W,
                              const float* __restrict__ gen_b) {
    int idx = blockIdx.x * blockDim.x + threadIdx.x;
    if (idx < 9 * 16384) {
        int e = idx >> 14;
        int p = idx & 16383;
        d_Gp[idx] = (e < 8) ? gen_W[p * 8 + e] : gen_b[p];
    } else {
        int j = idx - 9 * 16384;
        if (j < 9 * 128) {
            int e = j >> 7;
            int o = j & 127;
            d_WB[j] = (e < 8) ? gen_W[(NW + o) * 8 + e] : gen_b[NW + o];
        }
    }
}

// ---------------------------------------------------------------------------
// Main fused kernel: per block, 32 batch rows x 128 outputs.
//   c[b] = [prelu-MLP(features[b]), 1]  (9 coeffs)
//   out[b,o] = sum_e c[b,e] * (G_e x[b])[o] + sum_e c[b,e]*WB[e][o]
// ---------------------------------------------------------------------------
__global__ __launch_bounds__(256) void hyper_kernel(
    const float* __restrict__ x,
    const float* __restrict__ features,
    const float* __restrict__ fc0_W, const float* __restrict__ fc0_b,
    const float* __restrict__ a0p,
    const float* __restrict__ fc1_W, const float* __restrict__ fc1_b,
    const float* __restrict__ a1p,
    float* __restrict__ out)
{
    __shared__ float4 xsv[32 * 32];     // x tile: 32 rows x 128 cols (as float4)
    __shared__ float  cs[32][9];        // per-sample coefficients
    __shared__ float  wbs[9][128];      // bias generator

    const int tid = threadIdx.x;
    const int b0  = blockIdx.x * 32;

    // Cooperative load of x tile (coalesced float4)
    const float4* xg = (const float4*)(x + (size_t)b0 * IN_F);
    for (int k = tid; k < 32 * 32; k += 256) xsv[k] = xg[k];
    // Bias-generator table
    for (int k = tid; k < 9 * 128; k += 256) ((float*)wbs)[k] = d_WB[k];

    // Tiny MLP: one thread per sample (32 threads)
    if (tid < 32) {
        const int b = b0 + tid;
        const float a0 = a0p[0], a1 = a1p[0];
        float h0[16];
        #pragma unroll
        for (int j = 0; j < 16; j++) {
            float s = fc0_b[j];
            #pragma unroll
            for (int k = 0; k < 10; k++)
                s += features[b * 10 + k] * fc0_W[j * 10 + k];
            h0[j] = (s >= 0.f) ? s : a0 * s;
        }
        #pragma unroll
        for (int e = 0; e < 8; e++) {
            float s = fc1_b[e];
            #pragma unroll
            for (int j = 0; j < 16; j++)
                s += h0[j] * fc1_W[e * 16 + j];
            cs[tid][e] = (s >= 0.f) ? s : a1 * s;
        }
        cs[tid][8] = 1.f;
    }
    __syncthreads();

    const int og = tid & 31;   // warp lane -> output column group (coalesced stores)
    const int bg = tid >> 5;   // warp id  -> batch subgroup

    float acc[4][4];
    #pragma unroll
    for (int bi = 0; bi < 4; bi++)
        #pragma unroll
        for (int oi = 0; oi < 4; oi++) acc[bi][oi] = 0.f;

    for (int e = 0; e < 9; e++) {
        const float4* gb = (const float4*)(d_Gp + e * 16384);
        float cb[4];
        #pragma unroll
        for (int bi = 0; bi < 4; bi++) cb[bi] = cs[bg * 4 + bi][e];

        float z[4][4];
        #pragma unroll
        for (int bi = 0; bi < 4; bi++)
            #pragma unroll
            for (int oi = 0; oi < 4; oi++) z[bi][oi] = 0.f;

        #pragma unroll 2
        for (int i4 = 0; i4 < 32; i4++) {
            float4 g[4], xv[4];
            #pragma unroll
            for (int oi = 0; oi < 4; oi++)
                g[oi] = __ldg(gb + (og + 32 * oi) * 32 + i4);
            #pragma unroll
            for (int bi = 0; bi < 4; bi++)
                xv[bi] = xsv[(bg * 4 + bi) * 32 + i4];
            #pragma unroll
            for (int bi = 0; bi < 4; bi++)
                #pragma unroll
                for (int oi = 0; oi < 4; oi++) {
                    z[bi][oi] += xv[bi].x * g[oi].x;
                    z[bi][oi] += xv[bi].y * g[oi].y;
                    z[bi][oi] += xv[bi].z * g[oi].z;
                    z[bi][oi] += xv[bi].w * g[oi].w;
                }
        }
        #pragma unroll
        for (int bi = 0; bi < 4; bi++)
            #pragma unroll
            for (int oi = 0; oi < 4; oi++)
                acc[bi][oi] += cb[bi] * z[bi][oi];
    }

    // Per-sample bias: sum_e c[b,e] * WB[e][o]
    #pragma unroll
    for (int e = 0; e < 9; e++)
        #pragma unroll
        for (int bi = 0; bi < 4; bi++) {
            float cb = cs[bg * 4 + bi][e];
            #pragma unroll
            for (int oi = 0; oi < 4; oi++)
                acc[bi][oi] += cb * wbs[e][og + 32 * oi];
        }

    // Coalesced stores (lanes span o)
    #pragma unroll
    for (int bi = 0; bi < 4; bi++)
        #pragma unroll
        for (int oi = 0; oi < 4; oi++)
            out[(size_t)(b0 + bg * 4 + bi) * OUT_F + og + 32 * oi] = acc[bi][oi];
}

extern "C" void kernel_launch(void* const* d_in, const int* in_sizes, int n_in,
                              void* d_out, int out_size) {
    const float* x        = (const float*)d_in[0];
    const float* features = (const float*)d_in[1];
    const float* fc0_W    = (const float*)d_in[2];
    const float* fc0_b    = (const float*)d_in[3];
    const float* a0       = (const float*)d_in[4];
    const float* fc1_W    = (const float*)d_in[5];
    const float* fc1_b    = (const float*)d_in[6];
    const float* a1       = (const float*)d_in[7];
    const float* gen_W    = (const float*)d_in[8];
    const float* gen_b    = (const float*)d_in[9];
    float* out = (float*)d_out;

    const int total = 9 * 16384 + 9 * 128;
    repack_kernel<<<(total + 255) / 256, 256>>>(gen_W, gen_b);
    hyper_kernel<<<BATCH / 32, 256>>>(x, features, fc0_W, fc0_b, a0,
                                      fc1_W, fc1_b, a1, out);
}

// round 3
// speedup vs baseline: 1.0096x; 1.0096x over previous
#include <cuda_runtime.h>
#include <cuda_bf16.h>

#define BATCH 4096
#define IN_F 128
#define OUT_F 128
#define NW (IN_F * OUT_F)

// Scratch: 9 repacked generator matrices G_e[o][i] (e=8 holds gen_b weight part),
// plus bias-generator WB[e][o]. Static __device__ arrays (no runtime alloc).
__device__ float d_Gp[9 * 16384];
__device__ float d_WB[9 * 128];

// ---------------------------------------------------------------------------
// Repack: d_Gp[e][o*128+i] = gen_W[(o*128+i)*8 + e]  (e<8),  gen_b[o*128+i] (e=8)
//         d_WB[e][o]       = gen_W[(NW+o)*8 + e]     (e<8),  gen_b[NW+o]    (e=8)
// ---------------------------------------------------------------------------
__global__ void repack_kernel(const float* __restrict__ gen_W,
                              const float* __restrict__ gen_b) {
    int idx = blockIdx.x * blockDim.x + threadIdx.x;
    if (idx < 9 * 16384) {
        int e = idx >> 14;
        int p = idx & 16383;
        d_Gp[idx] = (e < 8) ? gen_W[p * 8 + e] : gen_b[p];
    } else {
        int j = idx - 9 * 16384;
        if (j < 9 * 128) {
            int e = j >> 7;
            int o = j & 127;
            d_WB[j] = (e < 8) ? gen_W[(NW + o) * 8 + e] : gen_b[NW + o];
        }
    }
}

// ---------------------------------------------------------------------------
// Main fused kernel: per block, 32 batch rows x 128 outputs.
//   c[b] = [prelu-MLP(features[b]), 1]  (9 coeffs)
//   out[b,o] = sum_e c[b,e] * (G_e x[b])[o] + sum_e c[b,e]*WB[e][o]
// ---------------------------------------------------------------------------
__global__ __launch_bounds__(256) void hyper_kernel(
    const float* __restrict__ x,
    const float* __restrict__ features,
    const float* __restrict__ fc0_W, const float* __restrict__ fc0_b,
    const float* __restrict__ a0p,
    const float* __restrict__ fc1_W, const float* __restrict__ fc1_b,
    const float* __restrict__ a1p,
    float* __restrict__ out)
{
    __shared__ float4 xsv[32 * 32];     // x tile: 32 rows x 128 cols (as float4)
    __shared__ float  cs[32][9];        // per-sample coefficients
    __shared__ float  wbs[9][128];      // bias generator

    const int tid = threadIdx.x;
    const int b0  = blockIdx.x * 32;

    // Cooperative load of x tile (coalesced float4)
    const float4* xg = (const float4*)(x + (size_t)b0 * IN_F);
    for (int k = tid; k < 32 * 32; k += 256) xsv[k] = xg[k];
    // Bias-generator table
    for (int k = tid; k < 9 * 128; k += 256) ((float*)wbs)[k] = d_WB[k];

    // Tiny MLP: one thread per sample (32 threads)
    if (tid < 32) {
        const int b = b0 + tid;
        const float a0 = a0p[0], a1 = a1p[0];
        float h0[16];
        #pragma unroll
        for (int j = 0; j < 16; j++) {
            float s = fc0_b[j];
            #pragma unroll
            for (int k = 0; k < 10; k++)
                s += features[b * 10 + k] * fc0_W[j * 10 + k];
            h0[j] = (s >= 0.f) ? s : a0 * s;
        }
        #pragma unroll
        for (int e = 0; e < 8; e++) {
            float s = fc1_b[e];
            #pragma unroll
            for (int j = 0; j < 16; j++)
                s += h0[j] * fc1_W[e * 16 + j];
            cs[tid][e] = (s >= 0.f) ? s : a1 * s;
        }
        cs[tid][8] = 1.f;
    }
    __syncthreads();

    const int og = tid & 31;   // warp lane -> output column group (coalesced stores)
    const int bg = tid >> 5;   // warp id  -> batch subgroup

    float acc[4][4];
    #pragma unroll
    for (int bi = 0; bi < 4; bi++)
        #pragma unroll
        for (int oi = 0; oi < 4; oi++) acc[bi][oi] = 0.f;

    for (int e = 0; e < 9; e++) {
        const float4* gb = (const float4*)(d_Gp + e * 16384);
        float cb[4];
        #pragma unroll
        for (int bi = 0; bi < 4; bi++) cb[bi] = cs[bg * 4 + bi][e];

        float z[4][4];
        #pragma unroll
        for (int bi = 0; bi < 4; bi++)
            #pragma unroll
            for (int oi = 0; oi < 4; oi++) z[bi][oi] = 0.f;

        #pragma unroll 2
        for (int i4 = 0; i4 < 32; i4++) {
            float4 g[4], xv[4];
            #pragma unroll
            for (int oi = 0; oi < 4; oi++)
                g[oi] = __ldg(gb + (og + 32 * oi) * 32 + i4);
            #pragma unroll
            for (int bi = 0; bi < 4; bi++)
                xv[bi] = xsv[(bg * 4 + bi) * 32 + i4];
            #pragma unroll
            for (int bi = 0; bi < 4; bi++)
                #pragma unroll
                for (int oi = 0; oi < 4; oi++) {
                    z[bi][oi] += xv[bi].x * g[oi].x;
                    z[bi][oi] += xv[bi].y * g[oi].y;
                    z[bi][oi] += xv[bi].z * g[oi].z;
                    z[bi][oi] += xv[bi].w * g[oi].w;
                }
        }
        #pragma unroll
        for (int bi = 0; bi < 4; bi++)
            #pragma unroll
            for (int oi = 0; oi < 4; oi++)
                acc[bi][oi] += cb[bi] * z[bi][oi];
    }

    // Per-sample bias: sum_e c[b,e] * WB[e][o]
    #pragma unroll
    for (int e = 0; e < 9; e++)
        #pragma unroll
        for (int bi = 0; bi < 4; bi++) {
            float cb = cs[bg * 4 + bi][e];
            #pragma unroll
            for (int oi = 0; oi < 4; oi++)
                acc[bi][oi] += cb * wbs[e][og + 32 * oi];
        }

    // Coalesced stores (lanes span o)
    #pragma unroll
    for (int bi = 0; bi < 4; bi++)
        #pragma unroll
        for (int oi = 0; oi < 4; oi++)
            out[(size_t)(b0 + bg * 4 + bi) * OUT_F + og + 32 * oi] = acc[bi][oi];
}

extern "C" void kernel_launch(void* const* d_in, const int* in_sizes, int n_in,
                              void* d_out, int out_size) {
    const float* x        = (const float*)d_in[0];
    const float* features = (const float*)d_in[1];
    const float* fc0_W    = (const float*)d_in[2];
    const float* fc0_b    = (const float*)d_in[3];
    const float* a0       = (const float*)d_in[4];
    const float* fc1_W    = (const float*)d_in[5];
    const float* fc1_b    = (const float*)d_in[6];
    const float* a1       = (const float*)d_in[7];
    const float* gen_W    = (const float*)d_in[8];
    const float* gen_b    = (const float*)d_in[9];
    float* out = (float*)d_out;

    const int total = 9 * 16384 + 9 * 128;
    repack_kernel<<<(total + 255) / 256, 256>>>(gen_W, gen_b);
    hyper_kernel<<<BATCH / 32, 256>>>(x, features, fc0_W, fc0_b, a0,
                                      fc1_W, fc1_b, a1, out);
}